// round 16
// baseline (speedup 1.0000x reference)
#include <cuda_runtime.h>
#include <cuda_bf16.h>
#include <cstdint>
#include <math.h>

#define NTOK    131072
#define KEXP    16
#define IN_DIM  256
#define OUT_DIM 128
#define TILE_M  128
#define MAX_TILES (NTOK / TILE_M + KEXP - 1)

#define KC      32                 // k elements per chunk
#define NCHUNK  (IN_DIM / KC)      // 8
#define AF      40                 // A row stride floats (conflict-free LDS.64)
#define AW      20                 // B row stride words (conflict-free LDS.32)
#define HBLKS   128                // hist/scatter blocks (256 thr x 4 tokens)

// ---------------- device scratch ----------------
__device__ int g_blockcnt[HBLKS][KEXP];
__device__ int g_perm[NTOK];
__device__ int g_tile_expert[MAX_TILES];
__device__ int g_tile_start[MAX_TILES];
__device__ int g_tile_len[MAX_TILES];
__device__ int g_num_tiles;
__device__ __nv_bfloat16 g_W1b[KEXP * OUT_DIM * IN_DIM];   // [e][n][k] bf16

// ---------------- helpers ----------------
__device__ __forceinline__ uint32_t smem_u32(const void* p) {
    uint32_t a;
    asm("{ .reg .u64 t; cvta.to.shared.u64 t, %1; cvt.u32.u64 %0, t; }" : "=r"(a) : "l"(p));
    return a;
}
__device__ __forceinline__ void cp_async16(uint32_t dst, const void* src) {
    asm volatile("cp.async.cg.shared.global [%0], [%1], 16;" :: "r"(dst), "l"(src) : "memory");
}
#define CP_COMMIT()  asm volatile("cp.async.commit_group;" ::: "memory")
#define CP_WAIT(n)   asm volatile("cp.async.wait_group %0;" :: "n"(n) : "memory")

__device__ __forceinline__ uint32_t pack_bf16(float lo, float hi) {
    uint32_t r;
    asm("cvt.rn.bf16x2.f32 %0, %1, %2;" : "=r"(r) : "f"(hi), "f"(lo));
    return r;
}
__device__ __forceinline__ void mma_bf16(float& d0, float& d1, float& d2, float& d3,
                                         uint32_t a0, uint32_t a1, uint32_t a2, uint32_t a3,
                                         uint32_t b0, uint32_t b1) {
    asm volatile(
        "mma.sync.aligned.m16n8k16.row.col.f32.bf16.bf16.f32 "
        "{%0,%1,%2,%3}, {%4,%5,%6,%7}, {%8,%9}, {%0,%1,%2,%3};"
        : "+f"(d0), "+f"(d1), "+f"(d2), "+f"(d3)
        : "r"(a0), "r"(a1), "r"(a2), "r"(a3), "r"(b0), "r"(b1));
}

// ---------------- 1. fused: hist per-block counts + coalesced W1 transform ----------
__global__ void fused_pre_kernel(const int* __restrict__ z, const float* __restrict__ W1) {
    __shared__ float t[256][17];
    __shared__ int sh[KEXP];
    int tid = threadIdx.x;

    if (blockIdx.x < HBLKS) {
        if (tid < KEXP) sh[tid] = 0;
        __syncthreads();
        int i = blockIdx.x * blockDim.x + tid;
        int4 v = ((const int4*)z)[i];
        atomicAdd(&sh[v.x], 1);
        atomicAdd(&sh[v.y], 1);
        atomicAdd(&sh[v.z], 1);
        atomicAdd(&sh[v.w], 1);
        __syncthreads();
        if (tid < KEXP) g_blockcnt[blockIdx.x][tid] = sh[tid];
    } else {
        int idx = blockIdx.x - HBLKS;
        int e     = idx >> 3;
        int strip = idx & 7;
        int n0 = strip * 16;
        int kq = tid >> 2;
        int nq = tid & 3;
#pragma unroll
        for (int p = 0; p < 4; p++) {
            int k = p * 64 + kq;
            float4 v = *(const float4*)(W1 + ((size_t)(e * IN_DIM + k) * OUT_DIM) + n0 + nq * 4);
            t[k][nq * 4 + 0] = v.x;
            t[k][nq * 4 + 1] = v.y;
            t[k][nq * 4 + 2] = v.z;
            t[k][nq * 4 + 3] = v.w;
        }
        __syncthreads();
        int kw = tid & 127;
        int nh = tid >> 7;
        uint32_t* dst = (uint32_t*)g_W1b;
#pragma unroll
        for (int p = 0; p < 8; p++) {
            int n = p * 2 + nh;
            uint32_t w = pack_bf16(t[kw * 2][n], t[kw * 2 + 1][n]);
            dst[((size_t)(e * OUT_DIM) + n0 + n) * (IN_DIM / 2) + kw] = w;
        }
    }
}

// ---------------- 2. scatter: bases from g_blockcnt (no scan kernel); block 0 builds tile table
__global__ void scatter_kernel(const int* __restrict__ z) {
    __shared__ int sh_cnt[KEXP];
    __shared__ int sh_base[KEXP];     // within-expert offset of this block
    __shared__ int s_off[KEXP + 1];   // expert bases (exclusive prefix of totals)
    __shared__ int s_tp[KEXP + 1];
    int tid = threadIdx.x;

    if (tid < KEXP) {
        int e = tid;
        int base = 0, total = 0;
#pragma unroll 8
        for (int b = 0; b < HBLKS; b++) {
            int c = g_blockcnt[b][e];
            if (b < (int)blockIdx.x) base += c;
            total += c;
        }
        sh_cnt[e]  = 0;
        sh_base[e] = base;
        s_off[e + 1] = total;
    }
    __syncthreads();
    if (tid == 0) {
        s_off[0] = 0;
        for (int e = 0; e < KEXP; e++) s_off[e + 1] += s_off[e];
    }
    __syncthreads();

    int i = blockIdx.x * blockDim.x + tid;
    int4 v = ((const int4*)z)[i];
    int r0 = atomicAdd(&sh_cnt[v.x], 1);
    int r1 = atomicAdd(&sh_cnt[v.y], 1);
    int r2 = atomicAdd(&sh_cnt[v.z], 1);
    int r3 = atomicAdd(&sh_cnt[v.w], 1);
    g_perm[s_off[v.x] + sh_base[v.x] + r0] = i * 4 + 0;
    g_perm[s_off[v.y] + sh_base[v.y] + r1] = i * 4 + 1;
    g_perm[s_off[v.z] + sh_base[v.z] + r2] = i * 4 + 2;
    g_perm[s_off[v.w] + sh_base[v.w] + r3] = i * 4 + 3;

    if (blockIdx.x == 0) {
        if (tid == 0) {
            int tp = 0;
            for (int e = 0; e < KEXP; e++) {
                s_tp[e] = tp;
                int c = s_off[e + 1] - s_off[e];
                tp += (c + TILE_M - 1) / TILE_M;
            }
            s_tp[KEXP] = tp;
            g_num_tiles = tp;
        }
        __syncthreads();
        int total = s_tp[KEXP];
        for (int idx = tid; idx < total; idx += blockDim.x) {
            int e = 0;
            while (s_tp[e + 1] <= idx) e++;
            int t = idx - s_tp[e];
            g_tile_expert[idx] = e;
            g_tile_start[idx] = s_off[e] + t * TILE_M;
            int rem = (s_off[e + 1] - s_off[e]) - t * TILE_M;
            g_tile_len[idx] = rem < TILE_M ? rem : TILE_M;
        }
    }
}

// ---------------- 3. bf16 HMMA MLP: 4-deep A + 3-deep B pipelines ----------------
struct MlpSmem {
    float    Af[4][TILE_M][AF];         // 81920 B
    uint32_t Bs[3][OUT_DIM][AW];        // 30720 B (pp overlays Bs[0] in epilogue)
    int    tok[TILE_M];
    float  b1v[OUT_DIM];
    float2 w2v[OUT_DIM];
};
#define DYN_SMEM ((int)sizeof(MlpSmem))

__global__ __launch_bounds__(256, 2)
void mlp_mma_kernel(const float* __restrict__ x,
                    const float* __restrict__ b1,
                    const float* __restrict__ W2,
                    const float* __restrict__ b2,
                    float* __restrict__ out)
{
    extern __shared__ char dyn[];
    MlpSmem* s = (MlpSmem*)dyn;

    int bid = blockIdx.x;
    if (bid >= g_num_tiles) return;
    int e     = g_tile_expert[bid];
    int start = g_tile_start[bid];
    int len   = g_tile_len[bid];

    int tid = threadIdx.x;
    int wid  = tid >> 5;
    int lane = tid & 31;
    int warp_m = wid >> 1;
    int warp_n = wid & 1;
    int r0 = lane >> 2;
    int cq = lane & 3;

    if (tid < TILE_M) {
        s->tok[tid] = g_perm[start + (tid < len ? tid : len - 1)];
        s->b1v[tid] = b1[e * OUT_DIM + tid];
        s->w2v[tid] = ((const float2*)(W2 + (size_t)e * OUT_DIM * 2))[tid];
    }
    __syncthreads();

    const __nv_bfloat16* W1be = g_W1b + (size_t)e * OUT_DIM * IN_DIM;

    // A staging: 8 lanes/row -> 4 rows x 128B contiguous per warp-instr (R13-proven)
    int ar = tid >> 3;
    int aq = tid & 7;
    const float* asrc[4];
#pragma unroll
    for (int p = 0; p < 4; p++)
        asrc[p] = x + (size_t)s->tok[p * 32 + ar] * IN_DIM + aq * 4;

    int bm = tid >> 1;
    int bq = (tid & 1) * 2;

    auto stageA = [&](int c) {
        int buf = c & 3;
#pragma unroll
        for (int p = 0; p < 4; p++)
            cp_async16(smem_u32(&s->Af[buf][p * 32 + ar][aq * 4]), asrc[p] + c * KC);
        CP_COMMIT();
    };
    auto stageB = [&](int c) {
        int buf = c - (c >= 3 ? 3 : 0) - (c >= 6 ? 3 : 0);
        const __nv_bfloat16* srcb = W1be + (size_t)bm * IN_DIM + c * KC;
        cp_async16(smem_u32(&s->Bs[buf][bm][bq * 4]),     srcb + bq * 8);
        cp_async16(smem_u32(&s->Bs[buf][bm][bq * 4 + 4]), srcb + bq * 8 + 8);
        CP_COMMIT();
    };

    float acc[2][8][4];
#pragma unroll
    for (int mt = 0; mt < 2; mt++)
#pragma unroll
        for (int nt = 0; nt < 8; nt++)
#pragma unroll
            for (int v = 0; v < 4; v++) acc[mt][nt][v] = 0.f;

    // prologue commit order: A0 B0 A1 B1 A2   (positions: A_i=2i+1, B_i=2i+2)
    stageA(0); stageB(0); stageA(1); stageB(1); stageA(2);

    int arow = warp_m * 32;
    int brow = warp_n * 64;

#pragma unroll
    for (int i = 0; i < NCHUNK; i++) {
        int abuf = i & 3;
        int bbuf = i - (i >= 3 ? 3 : 0) - (i >= 6 ? 3 : 0);
        // FIFO schedule: pending after (A_i,B_i) = 3 for i<6, 2 at i==6, 0 at i==7
        if (i < 6)      { CP_WAIT(3); }
        else if (i == 6){ CP_WAIT(2); }
        else            { CP_WAIT(0); }
        __syncthreads();                    // all threads past chunk i-1: its buffers free
        if (i + 2 < NCHUNK) stageB(i + 2);  // into B buf (i-1)%3
        if (i + 3 < NCHUNK) stageA(i + 3);  // into A buf (i-1)&3

#pragma unroll
        for (int ks = 0; ks < 2; ks++) {
            int kf = ks * 16;
            int kb = ks * 8;
            uint32_t af[2][4];
#pragma unroll
            for (int mt = 0; mt < 2; mt++) {
                int mr = arow + mt * 16;
                float2 f0 = *(const float2*)&s->Af[abuf][mr + r0    ][kf + cq * 2];
                float2 f1 = *(const float2*)&s->Af[abuf][mr + r0 + 8][kf + cq * 2];
                float2 f2 = *(const float2*)&s->Af[abuf][mr + r0    ][kf + 8 + cq * 2];
                float2 f3 = *(const float2*)&s->Af[abuf][mr + r0 + 8][kf + 8 + cq * 2];
                af[mt][0] = pack_bf16(f0.x, f0.y);
                af[mt][1] = pack_bf16(f1.x, f1.y);
                af[mt][2] = pack_bf16(f2.x, f2.y);
                af[mt][3] = pack_bf16(f3.x, f3.y);
            }
#pragma unroll
            for (int nt = 0; nt < 8; nt++) {
                uint32_t b0 = s->Bs[bbuf][brow + nt * 8 + r0][kb + cq    ];
                uint32_t b1f = s->Bs[bbuf][brow + nt * 8 + r0][kb + cq + 4];
#pragma unroll
                for (int mt = 0; mt < 2; mt++)
                    mma_bf16(acc[mt][nt][0], acc[mt][nt][1], acc[mt][nt][2], acc[mt][nt][3],
                             af[mt][0], af[mt][1], af[mt][2], af[mt][3], b0, b1f);
            }
        }
    }

    // epilogue; pp overlays Bs[0] (last read at chunk 6; all warps past it at iter-7 barrier)
    float2 (*pp)[2] = (float2(*)[2])&s->Bs[0][0][0];

    float p0[2][2], p1[2][2];
#pragma unroll
    for (int mt = 0; mt < 2; mt++)
#pragma unroll
        for (int h = 0; h < 2; h++) { p0[mt][h] = 0.f; p1[mt][h] = 0.f; }

#pragma unroll
    for (int nt = 0; nt < 8; nt++) {
        int c = warp_n * 64 + nt * 8 + cq * 2;
        float  ba = s->b1v[c], bb = s->b1v[c + 1];
        float2 wa = s->w2v[c], wb = s->w2v[c + 1];
#pragma unroll
        for (int mt = 0; mt < 2; mt++) {
            float h00 = fmaxf(acc[mt][nt][0] + ba, 0.f);
            float h01 = fmaxf(acc[mt][nt][1] + bb, 0.f);
            p0[mt][0] = fmaf(h00, wa.x, fmaf(h01, wb.x, p0[mt][0]));
            p1[mt][0] = fmaf(h00, wa.y, fmaf(h01, wb.y, p1[mt][0]));
            float h10 = fmaxf(acc[mt][nt][2] + ba, 0.f);
            float h11 = fmaxf(acc[mt][nt][3] + bb, 0.f);
            p0[mt][1] = fmaf(h10, wa.x, fmaf(h11, wb.x, p0[mt][1]));
            p1[mt][1] = fmaf(h10, wa.y, fmaf(h11, wb.y, p1[mt][1]));
        }
    }
#pragma unroll
    for (int mt = 0; mt < 2; mt++)
#pragma unroll
        for (int h = 0; h < 2; h++) {
            p0[mt][h] += __shfl_xor_sync(0xFFFFFFFFu, p0[mt][h], 1);
            p1[mt][h] += __shfl_xor_sync(0xFFFFFFFFu, p1[mt][h], 1);
            p0[mt][h] += __shfl_xor_sync(0xFFFFFFFFu, p0[mt][h], 2);
            p1[mt][h] += __shfl_xor_sync(0xFFFFFFFFu, p1[mt][h], 2);
        }
    if (cq == 0) {
#pragma unroll
        for (int mt = 0; mt < 2; mt++)
#pragma unroll
            for (int h = 0; h < 2; h++) {
                int row = warp_m * 32 + mt * 16 + h * 8 + r0;
                pp[row][warp_n] = make_float2(p0[mt][h], p1[mt][h]);
            }
    }
    __syncthreads();

    if (tid < TILE_M && tid < len) {
        float2 a = pp[tid][0], b = pp[tid][1];
        float l0 = a.x + b.x + b2[e * 2 + 0];
        float l1 = a.y + b.y + b2[e * 2 + 1];
        float mx = fmaxf(l0, l1);
        float e0 = expf(l0 - mx);
        float e1 = expf(l1 - mx);
        float inv = 1.f / (e0 + e1);
        ((float2*)out)[s->tok[tid]] = make_float2(e0 * inv, e1 * inv);
    }
}

// ---------------- launch ----------------
extern "C" void kernel_launch(void* const* d_in, const int* in_sizes, int n_in,
                              void* d_out, int out_size) {
    const float* x  = (const float*)d_in[0];
    const int*   z  = (const int*)d_in[1];
    const float* W1 = (const float*)d_in[2];
    const float* b1 = (const float*)d_in[3];
    const float* W2 = (const float*)d_in[4];
    const float* b2 = (const float*)d_in[5];
    float* out = (float*)d_out;

    cudaFuncSetAttribute(mlp_mma_kernel, cudaFuncAttributeMaxDynamicSharedMemorySize, DYN_SMEM);

    fused_pre_kernel<<<HBLKS + 128, 256>>>(z, W1);
    scatter_kernel<<<HBLKS, 256>>>(z);
    mlp_mma_kernel<<<MAX_TILES, 256, DYN_SMEM>>>(x, b1, W2, b2, out);
}

// round 17
// speedup vs baseline: 1.0870x; 1.0870x over previous
#include <cuda_runtime.h>
#include <cuda_bf16.h>
#include <cstdint>
#include <math.h>

#define NTOK    131072
#define KEXP    16
#define IN_DIM  256
#define OUT_DIM 128
#define TILE_M  128
#define MAX_TILES (NTOK / TILE_M + KEXP - 1)

#define KC      32                 // k elements per chunk
#define NCHUNK  (IN_DIM / KC)      // 8
#define AF      40                 // A row stride floats (conflict-free LDS.64)
#define AW      20                 // B row stride words (conflict-free LDS.32)
#define HBLKS   128                // hist blocks inside fused_pre

// ---------------- device scratch ----------------
__device__ int g_counts[KEXP];
__device__ int g_cursor[KEXP];
__device__ int g_perm[NTOK];
__device__ int g_tile_expert[MAX_TILES];
__device__ int g_tile_start[MAX_TILES];
__device__ int g_tile_len[MAX_TILES];
__device__ int g_num_tiles;
__device__ __nv_bfloat16 g_W1b[KEXP * OUT_DIM * IN_DIM];   // [e][n][k] bf16

// ---------------- helpers ----------------
__device__ __forceinline__ uint32_t smem_u32(const void* p) {
    uint32_t a;
    asm("{ .reg .u64 t; cvta.to.shared.u64 t, %1; cvt.u32.u64 %0, t; }" : "=r"(a) : "l"(p));
    return a;
}
__device__ __forceinline__ void cp_async16(uint32_t dst, const void* src) {
    asm volatile("cp.async.cg.shared.global [%0], [%1], 16;" :: "r"(dst), "l"(src) : "memory");
}
#define CP_COMMIT()  asm volatile("cp.async.commit_group;" ::: "memory")
#define CP_WAIT0()   asm volatile("cp.async.wait_group 0;" ::: "memory")
#define CP_WAIT1()   asm volatile("cp.async.wait_group 1;" ::: "memory")

__device__ __forceinline__ uint32_t pack_bf16(float lo, float hi) {
    uint32_t r;
    asm("cvt.rn.bf16x2.f32 %0, %1, %2;" : "=r"(r) : "f"(hi), "f"(lo));
    return r;
}
__device__ __forceinline__ void mma_bf16(float& d0, float& d1, float& d2, float& d3,
                                         uint32_t a0, uint32_t a1, uint32_t a2, uint32_t a3,
                                         uint32_t b0, uint32_t b1) {
    asm volatile(
        "mma.sync.aligned.m16n8k16.row.col.f32.bf16.bf16.f32 "
        "{%0,%1,%2,%3}, {%4,%5,%6,%7}, {%8,%9}, {%0,%1,%2,%3};"
        : "+f"(d0), "+f"(d1), "+f"(d2), "+f"(d3)
        : "r"(a0), "r"(a1), "r"(a2), "r"(a3), "r"(b0), "r"(b1));
}

// ---------------- 1. fused: hist + coalesced W1 transform (R13-identical) ----------
__global__ void fused_pre_kernel(const int* __restrict__ z, const float* __restrict__ W1) {
    __shared__ float t[256][17];
    __shared__ int sh[KEXP];
    int tid = threadIdx.x;

    if (blockIdx.x < HBLKS) {
        if (tid < KEXP) sh[tid] = 0;
        __syncthreads();
        int i = blockIdx.x * blockDim.x + tid;
        int4 v = ((const int4*)z)[i];
        atomicAdd(&sh[v.x], 1);
        atomicAdd(&sh[v.y], 1);
        atomicAdd(&sh[v.z], 1);
        atomicAdd(&sh[v.w], 1);
        __syncthreads();
        if (tid < KEXP) atomicAdd(&g_counts[tid], sh[tid]);
    } else {
        int idx = blockIdx.x - HBLKS;
        int e     = idx >> 3;
        int strip = idx & 7;
        int n0 = strip * 16;
        int kq = tid >> 2;
        int nq = tid & 3;
#pragma unroll
        for (int p = 0; p < 4; p++) {
            int k = p * 64 + kq;
            float4 v = *(const float4*)(W1 + ((size_t)(e * IN_DIM + k) * OUT_DIM) + n0 + nq * 4);
            t[k][nq * 4 + 0] = v.x;
            t[k][nq * 4 + 1] = v.y;
            t[k][nq * 4 + 2] = v.z;
            t[k][nq * 4 + 3] = v.w;
        }
        __syncthreads();
        int kw = tid & 127;
        int nh = tid >> 7;
        uint32_t* dst = (uint32_t*)g_W1b;
#pragma unroll
        for (int p = 0; p < 8; p++) {
            int n = p * 2 + nh;
            uint32_t w = pack_bf16(t[kw * 2][n], t[kw * 2 + 1][n]);
            dst[((size_t)(e * OUT_DIM) + n0 + n) * (IN_DIM / 2) + kw] = w;
        }
    }
}

// ---------------- 2. scan + T-MAJOR INTERLEAVED tile table ----------------
__global__ void scan_kernel() {
    __shared__ int s_off[KEXP];
    __shared__ int s_nt[KEXP];
    __shared__ int s_maxnt;
    int tid = threadIdx.x;
    if (tid == 0) {
        int off = 0, tp = 0, mx = 0;
        for (int e = 0; e < KEXP; e++) {
            s_off[e] = off;
            g_cursor[e] = off;
            int c = g_counts[e];
            int nt = (c + TILE_M - 1) / TILE_M;
            s_nt[e] = nt;
            off += c;
            tp += nt;
            if (nt > mx) mx = nt;
        }
        g_num_tiles = tp;
        s_maxnt = mx;
    }
    __syncthreads();
    int mx = s_maxnt;
    // emit tiles ordered by (t, e): concurrent CTAs then gather from the same
    // contiguous ~2MB token window -> DRAM page hits
    for (int p = tid; p < mx * KEXP; p += blockDim.x) {
        int e = p & (KEXP - 1);
        int t = p >> 4;
        if (t < s_nt[e]) {
            int idx = 0;
#pragma unroll
            for (int e2 = 0; e2 < KEXP; e2++) {
                int nt2 = s_nt[e2];
                idx += (t < nt2) ? t : nt2;
                if (e2 < e && nt2 > t) idx++;
            }
            g_tile_expert[idx] = e;
            g_tile_start[idx]  = s_off[e] + t * TILE_M;
            int rem = g_counts[e] - t * TILE_M;
            g_tile_len[idx] = rem < TILE_M ? rem : TILE_M;
        }
    }
}

// ---------------- 3. scatter (R13-identical) + reset g_counts ----------------
__global__ void scatter_kernel(const int* __restrict__ z) {
    __shared__ int sh_cnt[KEXP];
    __shared__ int sh_base[KEXP];
    int tid = threadIdx.x;
    if (blockIdx.x == 0 && tid < KEXP) g_counts[tid] = 0;
    if (tid < KEXP) sh_cnt[tid] = 0;
    __syncthreads();
    int i = blockIdx.x * blockDim.x + tid;
    int4 v = ((const int4*)z)[i];
    int r0 = atomicAdd(&sh_cnt[v.x], 1);
    int r1 = atomicAdd(&sh_cnt[v.y], 1);
    int r2 = atomicAdd(&sh_cnt[v.z], 1);
    int r3 = atomicAdd(&sh_cnt[v.w], 1);
    __syncthreads();
    if (tid < KEXP) {
        int c = sh_cnt[tid];
        sh_base[tid] = (c > 0) ? atomicAdd(&g_cursor[tid], c) : 0;
    }
    __syncthreads();
    g_perm[sh_base[v.x] + r0] = i * 4 + 0;
    g_perm[sh_base[v.y] + r1] = i * 4 + 1;
    g_perm[sh_base[v.z] + r2] = i * 4 + 2;
    g_perm[sh_base[v.w] + r3] = i * 4 + 3;
}

// ---------------- 4. bf16 HMMA MLP (R13-identical) ----------------
struct MlpSmem {
    float    Af[3][TILE_M][AF];         // x chunks fp32: 61440 B
    uint32_t Bs[3][OUT_DIM][AW];        // W1b chunks packed bf16x2: 30720 B
    int    tok[TILE_M];
    float  b1v[OUT_DIM];
    float2 w2v[OUT_DIM];
    float2 pp[TILE_M][2];
};
#define DYN_SMEM ((int)sizeof(MlpSmem))

__global__ __launch_bounds__(256, 2)
void mlp_mma_kernel(const float* __restrict__ x,
                    const float* __restrict__ b1,
                    const float* __restrict__ W2,
                    const float* __restrict__ b2,
                    float* __restrict__ out)
{
    extern __shared__ char dyn[];
    MlpSmem* s = (MlpSmem*)dyn;

    int bid = blockIdx.x;
    if (bid >= g_num_tiles) return;
    int e     = g_tile_expert[bid];
    int start = g_tile_start[bid];
    int len   = g_tile_len[bid];

    int tid = threadIdx.x;
    int wid  = tid >> 5;
    int lane = tid & 31;
    int warp_m = wid >> 1;
    int warp_n = wid & 1;
    int r0 = lane >> 2;
    int cq = lane & 3;

    if (tid < TILE_M) {
        s->tok[tid] = g_perm[start + (tid < len ? tid : len - 1)];
        s->b1v[tid] = b1[e * OUT_DIM + tid];
        s->w2v[tid] = ((const float2*)(W2 + (size_t)e * OUT_DIM * 2))[tid];
    }
    __syncthreads();

    const __nv_bfloat16* W1be = g_W1b + (size_t)e * OUT_DIM * IN_DIM;

    int ar = tid >> 3;
    int aq = tid & 7;
    const float* asrc[4];
#pragma unroll
    for (int p = 0; p < 4; p++)
        asrc[p] = x + (size_t)s->tok[p * 32 + ar] * IN_DIM + aq * 4;

    int bm = tid >> 1;
    int bq = (tid & 1) * 2;
    auto stage = [&](int c) {
        int buf = c - (c >= 3 ? 3 : 0) - (c >= 6 ? 3 : 0);
#pragma unroll
        for (int p = 0; p < 4; p++)
            cp_async16(smem_u32(&s->Af[buf][p * 32 + ar][aq * 4]), asrc[p] + c * KC);
        const __nv_bfloat16* srcb = W1be + (size_t)bm * IN_DIM + c * KC;
        cp_async16(smem_u32(&s->Bs[buf][bm][bq * 4]),     srcb + bq * 8);
        cp_async16(smem_u32(&s->Bs[buf][bm][bq * 4 + 4]), srcb + bq * 8 + 8);
        CP_COMMIT();
    };

    float acc[2][8][4];
#pragma unroll
    for (int mt = 0; mt < 2; mt++)
#pragma unroll
        for (int nt = 0; nt < 8; nt++)
#pragma unroll
            for (int v = 0; v < 4; v++) acc[mt][nt][v] = 0.f;

    stage(0);
    stage(1);

    int arow = warp_m * 32;
    int brow = warp_n * 64;

#pragma unroll
    for (int i = 0; i < NCHUNK; i++) {
        int buf = i % 3;
        if (i < NCHUNK - 1) { CP_WAIT1(); }
        else                { CP_WAIT0(); }
        __syncthreads();
        if (i + 2 < NCHUNK) stage(i + 2);

#pragma unroll
        for (int ks = 0; ks < 2; ks++) {
            int kf = ks * 16;
            int kb = ks * 8;
            uint32_t af[2][4];
#pragma unroll
            for (int mt = 0; mt < 2; mt++) {
                int mr = arow + mt * 16;
                float2 f0 = *(const float2*)&s->Af[buf][mr + r0    ][kf + cq * 2];
                float2 f1 = *(const float2*)&s->Af[buf][mr + r0 + 8][kf + cq * 2];
                float2 f2 = *(const float2*)&s->Af[buf][mr + r0    ][kf + 8 + cq * 2];
                float2 f3 = *(const float2*)&s->Af[buf][mr + r0 + 8][kf + 8 + cq * 2];
                af[mt][0] = pack_bf16(f0.x, f0.y);
                af[mt][1] = pack_bf16(f1.x, f1.y);
                af[mt][2] = pack_bf16(f2.x, f2.y);
                af[mt][3] = pack_bf16(f3.x, f3.y);
            }
#pragma unroll
            for (int nt = 0; nt < 8; nt++) {
                uint32_t b0 = s->Bs[buf][brow + nt * 8 + r0][kb + cq    ];
                uint32_t b1f = s->Bs[buf][brow + nt * 8 + r0][kb + cq + 4];
#pragma unroll
                for (int mt = 0; mt < 2; mt++)
                    mma_bf16(acc[mt][nt][0], acc[mt][nt][1], acc[mt][nt][2], acc[mt][nt][3],
                             af[mt][0], af[mt][1], af[mt][2], af[mt][3], b0, b1f);
            }
        }
    }

    float p0[2][2], p1[2][2];
#pragma unroll
    for (int mt = 0; mt < 2; mt++)
#pragma unroll
        for (int h = 0; h < 2; h++) { p0[mt][h] = 0.f; p1[mt][h] = 0.f; }

#pragma unroll
    for (int nt = 0; nt < 8; nt++) {
        int c = warp_n * 64 + nt * 8 + cq * 2;
        float  ba = s->b1v[c], bb = s->b1v[c + 1];
        float2 wa = s->w2v[c], wb = s->w2v[c + 1];
#pragma unroll
        for (int mt = 0; mt < 2; mt++) {
            float h00 = fmaxf(acc[mt][nt][0] + ba, 0.f);
            float h01 = fmaxf(acc[mt][nt][1] + bb, 0.f);
            p0[mt][0] = fmaf(h00, wa.x, fmaf(h01, wb.x, p0[mt][0]));
            p1[mt][0] = fmaf(h00, wa.y, fmaf(h01, wb.y, p1[mt][0]));
            float h10 = fmaxf(acc[mt][nt][2] + ba, 0.f);
            float h11 = fmaxf(acc[mt][nt][3] + bb, 0.f);
            p0[mt][1] = fmaf(h10, wa.x, fmaf(h11, wb.x, p0[mt][1]));
            p1[mt][1] = fmaf(h10, wa.y, fmaf(h11, wb.y, p1[mt][1]));
        }
    }
#pragma unroll
    for (int mt = 0; mt < 2; mt++)
#pragma unroll
        for (int h = 0; h < 2; h++) {
            p0[mt][h] += __shfl_xor_sync(0xFFFFFFFFu, p0[mt][h], 1);
            p1[mt][h] += __shfl_xor_sync(0xFFFFFFFFu, p1[mt][h], 1);
            p0[mt][h] += __shfl_xor_sync(0xFFFFFFFFu, p0[mt][h], 2);
            p1[mt][h] += __shfl_xor_sync(0xFFFFFFFFu, p1[mt][h], 2);
        }
    if (cq == 0) {
#pragma unroll
        for (int mt = 0; mt < 2; mt++)
#pragma unroll
            for (int h = 0; h < 2; h++) {
                int row = warp_m * 32 + mt * 16 + h * 8 + r0;
                s->pp[row][warp_n] = make_float2(p0[mt][h], p1[mt][h]);
            }
    }
    __syncthreads();

    if (tid < TILE_M && tid < len) {
        float2 a = s->pp[tid][0], b = s->pp[tid][1];
        float l0 = a.x + b.x + b2[e * 2 + 0];
        float l1 = a.y + b.y + b2[e * 2 + 1];
        float mx = fmaxf(l0, l1);
        float e0 = expf(l0 - mx);
        float e1 = expf(l1 - mx);
        float inv = 1.f / (e0 + e1);
        ((float2*)out)[s->tok[tid]] = make_float2(e0 * inv, e1 * inv);
    }
}

// ---------------- launch ----------------
extern "C" void kernel_launch(void* const* d_in, const int* in_sizes, int n_in,
                              void* d_out, int out_size) {
    const float* x  = (const float*)d_in[0];
    const int*   z  = (const int*)d_in[1];
    const float* W1 = (const float*)d_in[2];
    const float* b1 = (const float*)d_in[3];
    const float* W2 = (const float*)d_in[4];
    const float* b2 = (const float*)d_in[5];
    float* out = (float*)d_out;

    cudaFuncSetAttribute(mlp_mma_kernel, cudaFuncAttributeMaxDynamicSharedMemorySize, DYN_SMEM);

    fused_pre_kernel<<<HBLKS + 128, 256>>>(z, W1);
    scan_kernel<<<1, 256>>>();
    scatter_kernel<<<NTOK / 1024, 256>>>(z);
    mlp_mma_kernel<<<MAX_TILES, 256, DYN_SMEM>>>(x, b1, W2, b2, out);
}